// round 1
// baseline (speedup 1.0000x reference)
#include <cuda_runtime.h>
#include <math.h>

// ---------------- problem constants ----------------
#define NH    4
#define HD    256          // head dim == model dim
#define SEQ   1024
#define BATCH 8
#define MTOK  (BATCH*SEQ)  // 8192 token rows
#define FF    1024

// ---------------- scratch (__device__ globals; no allocation) ----------------
__device__ float g_q  [(size_t)NH*MTOK*HD];   // [h][b*S+s][d]
__device__ float g_k  [(size_t)NH*MTOK*HD];
__device__ float g_v  [(size_t)NH*MTOK*HD];
__device__ float g_att[(size_t)MTOK*NH*HD];   // [b*S+s][h*D+d]  (concat layout)
__device__ float g_x1 [(size_t)MTOK*HD];
__device__ float g_t1 [(size_t)MTOK*HD];      // reused: mh, then ff2 out
__device__ float g_hid[(size_t)MTOK*FF];

// ---------------- generic tiled GEMM: C[M,N] = A[M,K] * B[N,K]^T (+bias)(+relu) ----
// BM=BN=64, BK=16, 256 threads, 4x4 micro-tile per thread.
template<int RELU>
__global__ __launch_bounds__(256) void gemm64(
    const float* __restrict__ A, const float* __restrict__ Bw,
    const float* __restrict__ bias, float* __restrict__ C,
    int M, int N, int K)
{
    __shared__ float sA[16][68];
    __shared__ float sB[16][68];
    const int tid = threadIdx.x;
    const int tx = tid & 15, ty = tid >> 4;
    const int m0 = blockIdx.y << 6, n0 = blockIdx.x << 6;

    const int r  = tid >> 2;          // 0..63
    const int c4 = (tid & 3) << 2;    // 0,4,8,12
    const float* Ap = A  + (size_t)(m0 + r) * K + c4;
    const float* Bp = Bw + (size_t)(n0 + r) * K + c4;

    float acc[4][4] = {};

    for (int k0 = 0; k0 < K; k0 += 16) {
        float4 av = *(const float4*)(Ap + k0);
        float4 bv = *(const float4*)(Bp + k0);
        sA[c4+0][r] = av.x; sA[c4+1][r] = av.y; sA[c4+2][r] = av.z; sA[c4+3][r] = av.w;
        sB[c4+0][r] = bv.x; sB[c4+1][r] = bv.y; sB[c4+2][r] = bv.z; sB[c4+3][r] = bv.w;
        __syncthreads();
        #pragma unroll
        for (int kk = 0; kk < 16; kk++) {
            float4 a = *(const float4*)&sA[kk][ty << 2];
            float4 b = *(const float4*)&sB[kk][tx << 2];
            float a4[4] = {a.x, a.y, a.z, a.w};
            float b4[4] = {b.x, b.y, b.z, b.w};
            #pragma unroll
            for (int rr = 0; rr < 4; rr++)
                #pragma unroll
                for (int cc = 0; cc < 4; cc++)
                    acc[rr][cc] += a4[rr] * b4[cc];
        }
        __syncthreads();
    }

    float4 bb = make_float4(0.f, 0.f, 0.f, 0.f);
    if (bias) bb = *(const float4*)(bias + n0 + (tx << 2));
    #pragma unroll
    for (int rr = 0; rr < 4; rr++) {
        const int m = m0 + (ty << 2) + rr;
        float4 o;
        o.x = acc[rr][0] + bb.x;
        o.y = acc[rr][1] + bb.y;
        o.z = acc[rr][2] + bb.z;
        o.w = acc[rr][3] + bb.w;
        if (RELU) {
            o.x = fmaxf(o.x, 0.f); o.y = fmaxf(o.y, 0.f);
            o.z = fmaxf(o.z, 0.f); o.w = fmaxf(o.w, 0.f);
        }
        *(float4*)(C + (size_t)m * N + n0 + (tx << 2)) = o;
    }
}

// ---------------- flash attention (causal + padding mask), fp32 -----------------
// One CTA per (b,h, 64-row tile). Online softmax over 64-key tiles.
// Thread (tx,ty): score rows i=ty*4+rr, score cols j=cc*16+tx;
//                 output rows i=ty*4+rr, dims d = u*64 + tx*4 + c.
#define QSTR 260
#define SSTR 68
#define FLASH_SMEM ((3*64*QSTR + 64*SSTR) * (int)sizeof(float))   // 217,088 B

__global__ __launch_bounds__(256) void flash_kernel(
    const float* __restrict__ qb, const float* __restrict__ kb,
    const float* __restrict__ vb, const int* __restrict__ amask,
    float* __restrict__ outc)
{
    extern __shared__ float sm[];
    float* sQ = sm;
    float* sK = sQ + 64 * QSTR;
    float* sV = sK + 64 * QSTR;
    float* sS = sV + 64 * QSTR;
    __shared__ int sMk[64];
    __shared__ int sMq[64];

    const int tid = threadIdx.x;
    const int tx = tid & 15, ty = tid >> 4;
    const int bh = blockIdx.y;
    const int b = bh >> 2, h = bh & 3;
    const int m0 = blockIdx.x << 6;
    const size_t base = ((size_t)h * MTOK + (size_t)b * SEQ) * HD;
    const float* Q  = qb + base;
    const float* Kp = kb + base;
    const float* Vp = vb + base;

    // load Q tile (64 x 256)
    for (int idx = tid; idx < 64 * 64; idx += 256) {
        int r = idx >> 6, c = (idx & 63) << 2;
        *(float4*)&sQ[r * QSTR + c] = *(const float4*)(Q + (size_t)(m0 + r) * HD + c);
    }
    if (tid < 64) sMq[tid] = amask[b * SEQ + m0 + tid];

    float m_run[4], l_run[4], accO[4][16];
    #pragma unroll
    for (int rr = 0; rr < 4; rr++) {
        m_run[rr] = -1e30f; l_run[rr] = 0.f;
        #pragma unroll
        for (int u = 0; u < 16; u++) accO[rr][u] = 0.f;
    }

    const int ntiles = blockIdx.x + 1;   // causal: only tiles with j0 <= m0
    for (int t = 0; t < ntiles; t++) {
        const int j0 = t << 6;
        __syncthreads();
        for (int idx = tid; idx < 64 * 64; idx += 256) {
            int r = idx >> 6, c = (idx & 63) << 2;
            *(float4*)&sK[r * QSTR + c] = *(const float4*)(Kp + (size_t)(j0 + r) * HD + c);
            *(float4*)&sV[r * QSTR + c] = *(const float4*)(Vp + (size_t)(j0 + r) * HD + c);
        }
        if (tid < 64) sMk[tid] = amask[b * SEQ + j0 + tid];
        __syncthreads();

        // ---- scores ----
        float s[4][4] = {};
        for (int d = 0; d < HD; d += 4) {
            float4 qv[4], kv[4];
            #pragma unroll
            for (int rr = 0; rr < 4; rr++)
                qv[rr] = *(const float4*)&sQ[((ty << 2) + rr) * QSTR + d];
            #pragma unroll
            for (int cc = 0; cc < 4; cc++)
                kv[cc] = *(const float4*)&sK[((cc << 4) + tx) * QSTR + d];
            #pragma unroll
            for (int rr = 0; rr < 4; rr++)
                #pragma unroll
                for (int cc = 0; cc < 4; cc++)
                    s[rr][cc] += qv[rr].x * kv[cc].x + qv[rr].y * kv[cc].y
                               + qv[rr].z * kv[cc].z + qv[rr].w * kv[cc].w;
        }

        // ---- mask + online softmax (row group owned by 16 lanes, width-16 shuffles) ----
        #pragma unroll
        for (int rr = 0; rr < 4; rr++) {
            const int iloc = (ty << 2) + rr;
            const int gi = m0 + iloc;
            const int qm = sMq[iloc];
            float mx = -1e30f;
            #pragma unroll
            for (int cc = 0; cc < 4; cc++) {
                const int jloc = (cc << 4) + tx;
                const int gj = j0 + jloc;
                const bool ok = qm && sMk[jloc] && (gj <= gi);
                s[rr][cc] = ok ? s[rr][cc] * 0.0625f : -1e30f;   // 1/sqrt(256)
                mx = fmaxf(mx, s[rr][cc]);
            }
            #pragma unroll
            for (int off = 8; off; off >>= 1)
                mx = fmaxf(mx, __shfl_xor_sync(0xffffffffu, mx, off, 16));
            const float mnew = fmaxf(m_run[rr], mx);
            const float alpha = expf(m_run[rr] - mnew);
            m_run[rr] = mnew;
            float ps = 0.f;
            #pragma unroll
            for (int cc = 0; cc < 4; cc++) {
                const float p = expf(s[rr][cc] - mnew);
                s[rr][cc] = p; ps += p;
            }
            #pragma unroll
            for (int off = 8; off; off >>= 1)
                ps += __shfl_xor_sync(0xffffffffu, ps, off, 16);
            l_run[rr] = l_run[rr] * alpha + ps;
            #pragma unroll
            for (int u = 0; u < 16; u++) accO[rr][u] *= alpha;
            #pragma unroll
            for (int cc = 0; cc < 4; cc++)
                sS[iloc * SSTR + (cc << 4) + tx] = s[rr][cc];
        }
        __syncthreads();

        // ---- O += P * V ----
        for (int j = 0; j < 64; j++) {
            float4 v[4];
            #pragma unroll
            for (int u = 0; u < 4; u++)
                v[u] = *(const float4*)&sV[j * QSTR + (u << 6) + (tx << 2)];
            float p[4];
            #pragma unroll
            for (int rr = 0; rr < 4; rr++)
                p[rr] = sS[((ty << 2) + rr) * SSTR + j];
            #pragma unroll
            for (int rr = 0; rr < 4; rr++)
                #pragma unroll
                for (int u = 0; u < 4; u++) {
                    accO[rr][u*4+0] += p[rr] * v[u].x;
                    accO[rr][u*4+1] += p[rr] * v[u].y;
                    accO[rr][u*4+2] += p[rr] * v[u].z;
                    accO[rr][u*4+3] += p[rr] * v[u].w;
                }
        }
    }

    // ---- epilogue: normalize; fully-masked query rows -> 0 (matches reference) ----
    #pragma unroll
    for (int rr = 0; rr < 4; rr++) {
        const int iloc = (ty << 2) + rr;
        const int gi = m0 + iloc;
        const float inv = (sMq[iloc] && l_run[rr] > 0.f) ? (1.f / l_run[rr]) : 0.f;
        float* orow = outc + (size_t)(b * SEQ + gi) * (NH * HD) + h * HD;
        #pragma unroll
        for (int u = 0; u < 4; u++) {
            float4 o;
            o.x = accO[rr][u*4+0] * inv;
            o.y = accO[rr][u*4+1] * inv;
            o.z = accO[rr][u*4+2] * inv;
            o.w = accO[rr][u*4+3] * inv;
            *(float4*)(orow + (u << 6) + (tx << 2)) = o;
        }
    }
}

// ---------------- fused residual-add + LayerNorm (one block per token row) -------
__global__ __launch_bounds__(256) void add_ln_kernel(
    const float* __restrict__ a, const float* __restrict__ b2,
    const float* __restrict__ g, const float* __restrict__ be,
    float* __restrict__ out)
{
    __shared__ float red[16];
    const int row = blockIdx.x, t = threadIdx.x;
    const size_t off = (size_t)row * HD + t;
    const float v = a[off] + b2[off];
    float sv = v, sq = v * v;
    #pragma unroll
    for (int o = 16; o; o >>= 1) {
        sv += __shfl_xor_sync(0xffffffffu, sv, o);
        sq += __shfl_xor_sync(0xffffffffu, sq, o);
    }
    if ((t & 31) == 0) { red[t >> 5] = sv; red[8 + (t >> 5)] = sq; }
    __syncthreads();
    if (t == 0) {
        float s1 = 0.f, s2 = 0.f;
        #pragma unroll
        for (int i = 0; i < 8; i++) { s1 += red[i]; s2 += red[8 + i]; }
        red[0] = s1; red[8] = s2;
    }
    __syncthreads();
    const float mu  = red[0] * (1.f / 256.f);
    const float var = red[8] * (1.f / 256.f) - mu * mu;
    out[off] = (v - mu) * rsqrtf(var + 1e-5f) * g[t] + be[t];
}

// ---------------- launch ---------------------------------------------------------
extern "C" void kernel_launch(void* const* d_in, const int* in_sizes, int n_in,
                              void* d_out, int out_size)
{
    const float* x    = (const float*)d_in[0];
    const int*   am   = (const int*  )d_in[1];
    const float* wq   = (const float*)d_in[2];
    const float* wk   = (const float*)d_in[3];
    const float* wv   = (const float*)d_in[4];
    const float* wo_w = (const float*)d_in[5];
    const float* wo_b = (const float*)d_in[6];
    const float* ln1g = (const float*)d_in[7];
    const float* ln1b = (const float*)d_in[8];
    const float* f1w  = (const float*)d_in[9];
    const float* f1b  = (const float*)d_in[10];
    const float* f2w  = (const float*)d_in[11];
    const float* f2b  = (const float*)d_in[12];
    const float* ln2g = (const float*)d_in[13];
    const float* ln2b = (const float*)d_in[14];
    float* out = (float*)d_out;
    (void)in_sizes; (void)n_in; (void)out_size;

    float *pq, *pk, *pv, *patt, *px1, *pt1, *phid;
    cudaGetSymbolAddress((void**)&pq,   g_q);
    cudaGetSymbolAddress((void**)&pk,   g_k);
    cudaGetSymbolAddress((void**)&pv,   g_v);
    cudaGetSymbolAddress((void**)&patt, g_att);
    cudaGetSymbolAddress((void**)&px1,  g_x1);
    cudaGetSymbolAddress((void**)&pt1,  g_t1);
    cudaGetSymbolAddress((void**)&phid, g_hid);

    const dim3 blk(256);

    // ---- QKV projections: 12 GEMMs (M=8192, N=256, K=256) ----
    for (int h = 0; h < NH; h++) {
        const size_t woff = (size_t)h * HD * HD;
        const size_t ooff = (size_t)h * MTOK * HD;
        gemm64<0><<<dim3(4, 128), blk>>>(x, wq + woff, nullptr, pq + ooff, MTOK, HD, HD);
        gemm64<0><<<dim3(4, 128), blk>>>(x, wk + woff, nullptr, pk + ooff, MTOK, HD, HD);
        gemm64<0><<<dim3(4, 128), blk>>>(x, wv + woff, nullptr, pv + ooff, MTOK, HD, HD);
    }

    // ---- causal flash attention ----
    cudaFuncSetAttribute(flash_kernel, cudaFuncAttributeMaxDynamicSharedMemorySize, FLASH_SMEM);
    flash_kernel<<<dim3(SEQ / 64, BATCH * NH), blk, FLASH_SMEM>>>(pq, pk, pv, am, patt);

    // ---- output projection + residual/LN1 ----
    gemm64<0><<<dim3(4, 128), blk>>>(patt, wo_w, wo_b, pt1, MTOK, HD, NH * HD);
    add_ln_kernel<<<MTOK, blk>>>(x, pt1, ln1g, ln1b, px1);

    // ---- FFN + residual/LN2 ----
    gemm64<1><<<dim3(16, 128), blk>>>(px1, f1w, f1b, phid, MTOK, FF, HD);
    gemm64<0><<<dim3(4, 128), blk>>>(phid, f2w, f2b, pt1, MTOK, HD, FF);
    add_ln_kernel<<<MTOK, blk>>>(px1, pt1, ln2g, ln2b, out);
}

// round 2
// speedup vs baseline: 1.5017x; 1.5017x over previous
#include <cuda_runtime.h>
#include <cuda_bf16.h>
#include <math.h>

// ---------------- problem constants ----------------
#define NH    4
#define HD    256
#define SEQ   1024
#define BATCH 8
#define MTOK  (BATCH*SEQ)
#define FF    1024

// ---------------- scratch ----------------
__device__ float g_q  [(size_t)NH*MTOK*HD];
__device__ float g_k  [(size_t)NH*MTOK*HD];
__device__ float g_v  [(size_t)NH*MTOK*HD];
__device__ float g_att[(size_t)MTOK*NH*HD];
__device__ float g_x1 [(size_t)MTOK*HD];
__device__ float g_t1 [(size_t)MTOK*HD];
__device__ float g_hid[(size_t)MTOK*FF];

// =================================================================
// bf16x3 split-precision tensor-core GEMM: C[M,N] = A[M,K]*B[N,K]^T
// Tiles: BM=128, BN=128, BK=32. 256 threads (8 warps of 64x32).
// =================================================================
#define ASTR 40   // smem row stride in bf16 elems (32 + 8 pad): conflict-free frags
#define GEMM_SMEM (2*2*128*ASTR*2*2)   // 2 operands * 2 bufs * 2 splits * 128*40 * 2B = 81920

__device__ __forceinline__ void mma16816(float* c, const unsigned* a, const unsigned* b)
{
    asm volatile(
        "mma.sync.aligned.m16n8k16.row.col.f32.bf16.bf16.f32 "
        "{%0,%1,%2,%3}, {%4,%5,%6,%7}, {%8,%9}, {%0,%1,%2,%3};\n"
        : "+f"(c[0]), "+f"(c[1]), "+f"(c[2]), "+f"(c[3])
        : "r"(a[0]), "r"(a[1]), "r"(a[2]), "r"(a[3]), "r"(b[0]), "r"(b[1]));
}

__device__ __forceinline__ unsigned ld32s(const __nv_bfloat16* p)
{
    return *reinterpret_cast<const unsigned*>(p);
}

// split a float4 into hi/lo bf16 pairs and store 8B each
__device__ __forceinline__ void split_store(__nv_bfloat16* hi_p, __nv_bfloat16* lo_p, float4 v)
{
    __nv_bfloat16 hx = __float2bfloat16_rn(v.x);
    __nv_bfloat16 hy = __float2bfloat16_rn(v.y);
    __nv_bfloat16 hz = __float2bfloat16_rn(v.z);
    __nv_bfloat16 hw = __float2bfloat16_rn(v.w);
    float lx = v.x - __bfloat162float(hx);
    float ly = v.y - __bfloat162float(hy);
    float lz = v.z - __bfloat162float(hz);
    float lw = v.w - __bfloat162float(hw);
    __nv_bfloat162 h01 = __halves2bfloat162(hx, hy);
    __nv_bfloat162 h23 = __halves2bfloat162(hz, hw);
    __nv_bfloat162 l01 = __floats2bfloat162_rn(lx, ly);
    __nv_bfloat162 l23 = __floats2bfloat162_rn(lz, lw);
    uint2 uh, ul;
    uh.x = *reinterpret_cast<unsigned*>(&h01);
    uh.y = *reinterpret_cast<unsigned*>(&h23);
    ul.x = *reinterpret_cast<unsigned*>(&l01);
    ul.y = *reinterpret_cast<unsigned*>(&l23);
    *reinterpret_cast<uint2*>(hi_p) = uh;
    *reinterpret_cast<uint2*>(lo_p) = ul;
}

template<int RELU>
__device__ __forceinline__ void gemm_core(
    const float* __restrict__ A, const float* __restrict__ Bw,
    const float* __restrict__ bias, float* __restrict__ C,
    int N, int K, int m0, int n0)
{
    extern __shared__ __nv_bfloat16 sm_bf[];
    __nv_bfloat16* sA = sm_bf;                      // [buf][split][128][ASTR]
    __nv_bfloat16* sB = sm_bf + 2*2*128*ASTR;

    const int tid  = threadIdx.x;
    const int lane = tid & 31, warp = tid >> 5;
    const int wm = (warp >> 2) << 6;   // 0 / 64
    const int wn = (warp & 3)  << 5;   // 0..96
    const int g = lane >> 2, t = lane & 3;
    const int KT = K >> 5;

    float acc[4][4][4];
    #pragma unroll
    for (int i = 0; i < 4; i++)
        #pragma unroll
        for (int j = 0; j < 4; j++)
            #pragma unroll
            for (int q = 0; q < 4; q++) acc[i][j][q] = 0.f;

    float4 rA[4], rB[4];
    const float* Ag = A  + (size_t)m0 * K;
    const float* Bg = Bw + (size_t)n0 * K;

    // prologue: tile 0
    #pragma unroll
    for (int i = 0; i < 4; i++) {
        int idx = i * 256 + tid;
        int r = idx >> 3, c = (idx & 7) << 2;
        rA[i] = *(const float4*)(Ag + (size_t)r * K + c);
        rB[i] = *(const float4*)(Bg + (size_t)r * K + c);
    }
    #pragma unroll
    for (int i = 0; i < 4; i++) {
        int idx = i * 256 + tid;
        int r = idx >> 3, c = (idx & 7) << 2;
        split_store(&sA[(0*128 + r)*ASTR + c], &sA[(1*128 + r)*ASTR + c], rA[i]);
        split_store(&sB[(0*128 + r)*ASTR + c], &sB[(1*128 + r)*ASTR + c], rB[i]);
    }
    __syncthreads();

    for (int kt = 0; kt < KT; kt++) {
        const int buf = kt & 1;
        if (kt + 1 < KT) {
            const int ko = (kt + 1) << 5;
            #pragma unroll
            for (int i = 0; i < 4; i++) {
                int idx = i * 256 + tid;
                int r = idx >> 3, c = (idx & 7) << 2;
                rA[i] = *(const float4*)(Ag + (size_t)r * K + ko + c);
                rB[i] = *(const float4*)(Bg + (size_t)r * K + ko + c);
            }
        }

        // ---- compute on buf ----
        #pragma unroll
        for (int ks = 0; ks < 2; ks++) {
            const int kc = (ks << 4) + (t << 1);
            unsigned ah[4][4], al[4][4], bh[4][2], bl[4][2];
            #pragma unroll
            for (int mt = 0; mt < 4; mt++) {
                const int r = wm + (mt << 4) + g;
                const __nv_bfloat16* ph = &sA[((buf*2 + 0)*128 + r)*ASTR + kc];
                const __nv_bfloat16* pl = &sA[((buf*2 + 1)*128 + r)*ASTR + kc];
                ah[mt][0] = ld32s(ph);             ah[mt][1] = ld32s(ph + 8*ASTR);
                ah[mt][2] = ld32s(ph + 8);         ah[mt][3] = ld32s(ph + 8*ASTR + 8);
                al[mt][0] = ld32s(pl);             al[mt][1] = ld32s(pl + 8*ASTR);
                al[mt][2] = ld32s(pl + 8);         al[mt][3] = ld32s(pl + 8*ASTR + 8);
            }
            #pragma unroll
            for (int nt = 0; nt < 4; nt++) {
                const int r = wn + (nt << 3) + g;
                const __nv_bfloat16* ph = &sB[((buf*2 + 0)*128 + r)*ASTR + kc];
                const __nv_bfloat16* pl = &sB[((buf*2 + 1)*128 + r)*ASTR + kc];
                bh[nt][0] = ld32s(ph); bh[nt][1] = ld32s(ph + 8);
                bl[nt][0] = ld32s(pl); bl[nt][1] = ld32s(pl + 8);
            }
            #pragma unroll
            for (int mt = 0; mt < 4; mt++)
                #pragma unroll
                for (int nt = 0; nt < 4; nt++) {
                    mma16816(acc[mt][nt], ah[mt], bh[nt]);
                    mma16816(acc[mt][nt], ah[mt], bl[nt]);
                    mma16816(acc[mt][nt], al[mt], bh[nt]);
                }
        }

        if (kt + 1 < KT) {
            const int nb = buf ^ 1;
            #pragma unroll
            for (int i = 0; i < 4; i++) {
                int idx = i * 256 + tid;
                int r = idx >> 3, c = (idx & 7) << 2;
                split_store(&sA[((nb*2 + 0)*128 + r)*ASTR + c],
                            &sA[((nb*2 + 1)*128 + r)*ASTR + c], rA[i]);
                split_store(&sB[((nb*2 + 0)*128 + r)*ASTR + c],
                            &sB[((nb*2 + 1)*128 + r)*ASTR + c], rB[i]);
            }
        }
        __syncthreads();
    }

    // ---- epilogue ----
    #pragma unroll
    for (int mt = 0; mt < 4; mt++) {
        const int row = m0 + wm + (mt << 4) + g;
        #pragma unroll
        for (int nt = 0; nt < 4; nt++) {
            const int col = n0 + wn + (nt << 3) + (t << 1);
            float bx = 0.f, by = 0.f;
            if (bias) { bx = bias[col]; by = bias[col + 1]; }
            float2 o0, o1;
            o0.x = acc[mt][nt][0] + bx;  o0.y = acc[mt][nt][1] + by;
            o1.x = acc[mt][nt][2] + bx;  o1.y = acc[mt][nt][3] + by;
            if (RELU) {
                o0.x = fmaxf(o0.x, 0.f); o0.y = fmaxf(o0.y, 0.f);
                o1.x = fmaxf(o1.x, 0.f); o1.y = fmaxf(o1.y, 0.f);
            }
            *(float2*)(C + (size_t)row * N + col)       = o0;
            *(float2*)(C + (size_t)(row + 8) * N + col) = o1;
        }
    }
}

template<int RELU>
__global__ __launch_bounds__(256, 1) void gemm_mma_kernel(
    const float* __restrict__ A, const float* __restrict__ Bw,
    const float* __restrict__ bias, float* __restrict__ C, int N, int K)
{
    gemm_core<RELU>(A, Bw, bias, C, N, K, blockIdx.y << 7, blockIdx.x << 7);
}

// batched QKV: grid.z in [0,12): mat = z/4 (q,k,v), head = z%4
__global__ __launch_bounds__(256, 1) void gemm_qkv_kernel(
    const float* __restrict__ x,
    const float* __restrict__ wq, const float* __restrict__ wk, const float* __restrict__ wv,
    float* __restrict__ oq, float* __restrict__ ok, float* __restrict__ ov)
{
    const int z = blockIdx.z;
    const int mat = z >> 2, h = z & 3;
    const float* Bw = (mat == 0 ? wq : mat == 1 ? wk : wv) + (size_t)h * HD * HD;
    float* C = (mat == 0 ? oq : mat == 1 ? ok : ov) + (size_t)h * MTOK * HD;
    gemm_core<0>(x, Bw, nullptr, C, HD, HD, blockIdx.y << 7, blockIdx.x << 7);
}

// ---------------- flash attention (causal + padding mask), fp32 -----------------
#define QSTR 260
#define SSTR 68
#define FLASH_SMEM ((3*64*QSTR + 64*SSTR) * (int)sizeof(float))

__global__ __launch_bounds__(256) void flash_kernel(
    const float* __restrict__ qb, const float* __restrict__ kb,
    const float* __restrict__ vb, const int* __restrict__ amask,
    float* __restrict__ outc)
{
    extern __shared__ float sm[];
    float* sQ = sm;
    float* sK = sQ + 64 * QSTR;
    float* sV = sK + 64 * QSTR;
    float* sS = sV + 64 * QSTR;
    __shared__ int sMk[64];
    __shared__ int sMq[64];

    const int tid = threadIdx.x;
    const int tx = tid & 15, ty = tid >> 4;
    const int bh = blockIdx.y;
    const int b = bh >> 2, h = bh & 3;
    const int m0 = blockIdx.x << 6;
    const size_t base = ((size_t)h * MTOK + (size_t)b * SEQ) * HD;
    const float* Q  = qb + base;
    const float* Kp = kb + base;
    const float* Vp = vb + base;

    for (int idx = tid; idx < 64 * 64; idx += 256) {
        int r = idx >> 6, c = (idx & 63) << 2;
        *(float4*)&sQ[r * QSTR + c] = *(const float4*)(Q + (size_t)(m0 + r) * HD + c);
    }
    if (tid < 64) sMq[tid] = amask[b * SEQ + m0 + tid];

    float m_run[4], l_run[4], accO[4][16];
    #pragma unroll
    for (int rr = 0; rr < 4; rr++) {
        m_run[rr] = -1e30f; l_run[rr] = 0.f;
        #pragma unroll
        for (int u = 0; u < 16; u++) accO[rr][u] = 0.f;
    }

    const int ntiles = blockIdx.x + 1;
    for (int t = 0; t < ntiles; t++) {
        const int j0 = t << 6;
        __syncthreads();
        for (int idx = tid; idx < 64 * 64; idx += 256) {
            int r = idx >> 6, c = (idx & 63) << 2;
            *(float4*)&sK[r * QSTR + c] = *(const float4*)(Kp + (size_t)(j0 + r) * HD + c);
            *(float4*)&sV[r * QSTR + c] = *(const float4*)(Vp + (size_t)(j0 + r) * HD + c);
        }
        if (tid < 64) sMk[tid] = amask[b * SEQ + j0 + tid];
        __syncthreads();

        float s[4][4] = {};
        for (int d = 0; d < HD; d += 4) {
            float4 qv[4], kv[4];
            #pragma unroll
            for (int rr = 0; rr < 4; rr++)
                qv[rr] = *(const float4*)&sQ[((ty << 2) + rr) * QSTR + d];
            #pragma unroll
            for (int cc = 0; cc < 4; cc++)
                kv[cc] = *(const float4*)&sK[((cc << 4) + tx) * QSTR + d];
            #pragma unroll
            for (int rr = 0; rr < 4; rr++)
                #pragma unroll
                for (int cc = 0; cc < 4; cc++)
                    s[rr][cc] += qv[rr].x * kv[cc].x + qv[rr].y * kv[cc].y
                               + qv[rr].z * kv[cc].z + qv[rr].w * kv[cc].w;
        }

        #pragma unroll
        for (int rr = 0; rr < 4; rr++) {
            const int iloc = (ty << 2) + rr;
            const int gi = m0 + iloc;
            const int qm = sMq[iloc];
            float mx = -1e30f;
            #pragma unroll
            for (int cc = 0; cc < 4; cc++) {
                const int jloc = (cc << 4) + tx;
                const int gj = j0 + jloc;
                const bool ok = qm && sMk[jloc] && (gj <= gi);
                s[rr][cc] = ok ? s[rr][cc] * 0.0625f : -1e30f;
                mx = fmaxf(mx, s[rr][cc]);
            }
            #pragma unroll
            for (int off = 8; off; off >>= 1)
                mx = fmaxf(mx, __shfl_xor_sync(0xffffffffu, mx, off, 16));
            const float mnew = fmaxf(m_run[rr], mx);
            const float alpha = expf(m_run[rr] - mnew);
            m_run[rr] = mnew;
            float ps = 0.f;
            #pragma unroll
            for (int cc = 0; cc < 4; cc++) {
                const float p = expf(s[rr][cc] - mnew);
                s[rr][cc] = p; ps += p;
            }
            #pragma unroll
            for (int off = 8; off; off >>= 1)
                ps += __shfl_xor_sync(0xffffffffu, ps, off, 16);
            l_run[rr] = l_run[rr] * alpha + ps;
            #pragma unroll
            for (int u = 0; u < 16; u++) accO[rr][u] *= alpha;
            #pragma unroll
            for (int cc = 0; cc < 4; cc++)
                sS[iloc * SSTR + (cc << 4) + tx] = s[rr][cc];
        }
        __syncthreads();

        for (int j = 0; j < 64; j++) {
            float4 v[4];
            #pragma unroll
            for (int u = 0; u < 4; u++)
                v[u] = *(const float4*)&sV[j * QSTR + (u << 6) + (tx << 2)];
            float p[4];
            #pragma unroll
            for (int rr = 0; rr < 4; rr++)
                p[rr] = sS[((ty << 2) + rr) * SSTR + j];
            #pragma unroll
            for (int rr = 0; rr < 4; rr++)
                #pragma unroll
                for (int u = 0; u < 4; u++) {
                    accO[rr][u*4+0] += p[rr] * v[u].x;
                    accO[rr][u*4+1] += p[rr] * v[u].y;
                    accO[rr][u*4+2] += p[rr] * v[u].z;
                    accO[rr][u*4+3] += p[rr] * v[u].w;
                }
        }
    }

    #pragma unroll
    for (int rr = 0; rr < 4; rr++) {
        const int iloc = (ty << 2) + rr;
        const int gi = m0 + iloc;
        const float inv = (sMq[iloc] && l_run[rr] > 0.f) ? (1.f / l_run[rr]) : 0.f;
        float* orow = outc + (size_t)(b * SEQ + gi) * (NH * HD) + h * HD;
        #pragma unroll
        for (int u = 0; u < 4; u++) {
            float4 o;
            o.x = accO[rr][u*4+0] * inv;
            o.y = accO[rr][u*4+1] * inv;
            o.z = accO[rr][u*4+2] * inv;
            o.w = accO[rr][u*4+3] * inv;
            *(float4*)(orow + (u << 6) + (tx << 2)) = o;
        }
    }
}

// ---------------- fused residual-add + LayerNorm ----------------
__global__ __launch_bounds__(256) void add_ln_kernel(
    const float* __restrict__ a, const float* __restrict__ b2,
    const float* __restrict__ g, const float* __restrict__ be,
    float* __restrict__ out)
{
    __shared__ float red[16];
    const int row = blockIdx.x, t = threadIdx.x;
    const size_t off = (size_t)row * HD + t;
    const float v = a[off] + b2[off];
    float sv = v, sq = v * v;
    #pragma unroll
    for (int o = 16; o; o >>= 1) {
        sv += __shfl_xor_sync(0xffffffffu, sv, o);
        sq += __shfl_xor_sync(0xffffffffu, sq, o);
    }
    if ((t & 31) == 0) { red[t >> 5] = sv; red[8 + (t >> 5)] = sq; }
    __syncthreads();
    if (t == 0) {
        float s1 = 0.f, s2 = 0.f;
        #pragma unroll
        for (int i = 0; i < 8; i++) { s1 += red[i]; s2 += red[8 + i]; }
        red[0] = s1; red[8] = s2;
    }
    __syncthreads();
    const float mu  = red[0] * (1.f / 256.f);
    const float var = red[8] * (1.f / 256.f) - mu * mu;
    out[off] = (v - mu) * rsqrtf(var + 1e-5f) * g[t] + be[t];
}

// ---------------- launch ----------------
extern "C" void kernel_launch(void* const* d_in, const int* in_sizes, int n_in,
                              void* d_out, int out_size)
{
    const float* x    = (const float*)d_in[0];
    const int*   am   = (const int*  )d_in[1];
    const float* wq   = (const float*)d_in[2];
    const float* wk   = (const float*)d_in[3];
    const float* wv   = (const float*)d_in[4];
    const float* wo_w = (const float*)d_in[5];
    const float* wo_b = (const float*)d_in[6];
    const float* ln1g = (const float*)d_in[7];
    const float* ln1b = (const float*)d_in[8];
    const float* f1w  = (const float*)d_in[9];
    const float* f1b  = (const float*)d_in[10];
    const float* f2w  = (const float*)d_in[11];
    const float* f2b  = (const float*)d_in[12];
    const float* ln2g = (const float*)d_in[13];
    const float* ln2b = (const float*)d_in[14];
    float* out = (float*)d_out;
    (void)in_sizes; (void)n_in; (void)out_size;

    float *pq, *pk, *pv, *patt, *px1, *pt1, *phid;
    cudaGetSymbolAddress((void**)&pq,   g_q);
    cudaGetSymbolAddress((void**)&pk,   g_k);
    cudaGetSymbolAddress((void**)&pv,   g_v);
    cudaGetSymbolAddress((void**)&patt, g_att);
    cudaGetSymbolAddress((void**)&px1,  g_x1);
    cudaGetSymbolAddress((void**)&pt1,  g_t1);
    cudaGetSymbolAddress((void**)&phid, g_hid);

    cudaFuncSetAttribute(gemm_qkv_kernel,   cudaFuncAttributeMaxDynamicSharedMemorySize, GEMM_SMEM);
    cudaFuncSetAttribute(gemm_mma_kernel<0>, cudaFuncAttributeMaxDynamicSharedMemorySize, GEMM_SMEM);
    cudaFuncSetAttribute(gemm_mma_kernel<1>, cudaFuncAttributeMaxDynamicSharedMemorySize, GEMM_SMEM);
    cudaFuncSetAttribute(flash_kernel,      cudaFuncAttributeMaxDynamicSharedMemorySize, FLASH_SMEM);

    const dim3 blk(256);

    // ---- QKV projections: one batched launch (12 GEMMs) ----
    gemm_qkv_kernel<<<dim3(HD/128, MTOK/128, 12), blk, GEMM_SMEM>>>(x, wq, wk, wv, pq, pk, pv);

    // ---- causal flash attention ----
    flash_kernel<<<dim3(SEQ / 64, BATCH * NH), blk, FLASH_SMEM>>>(pq, pk, pv, am, patt);

    // ---- output projection + residual/LN1 ----
    gemm_mma_kernel<0><<<dim3(HD/128, MTOK/128), blk, GEMM_SMEM>>>(patt, wo_w, wo_b, pt1, HD, NH*HD);
    add_ln_kernel<<<MTOK, blk>>>(x, pt1, ln1g, ln1b, px1);

    // ---- FFN + residual/LN2 ----
    gemm_mma_kernel<1><<<dim3(FF/128, MTOK/128), blk, GEMM_SMEM>>>(px1, f1w, f1b, phid, FF, HD);
    gemm_mma_kernel<0><<<dim3(HD/128, MTOK/128), blk, GEMM_SMEM>>>(phid, f2w, f2b, pt1, HD, FF);
    add_ln_kernel<<<MTOK, blk>>>(px1, pt1, ln2g, ln2b, out);
}

// round 4
// speedup vs baseline: 2.6163x; 1.7422x over previous
#include <cuda_runtime.h>
#include <cuda_bf16.h>
#include <math.h>

// ---------------- problem constants ----------------
#define NH    4
#define HD    256
#define SEQ   1024
#define BATCH 8
#define MTOK  (BATCH*SEQ)
#define FF    1024

// ---------------- scratch ----------------
__device__ __nv_bfloat16 g_qh[(size_t)NH*MTOK*HD];
__device__ __nv_bfloat16 g_ql[(size_t)NH*MTOK*HD];
__device__ __nv_bfloat16 g_kh[(size_t)NH*MTOK*HD];
__device__ __nv_bfloat16 g_kl[(size_t)NH*MTOK*HD];
__device__ __nv_bfloat16 g_vh[(size_t)NH*MTOK*HD];
__device__ __nv_bfloat16 g_vl[(size_t)NH*MTOK*HD];
__device__ float g_att[(size_t)MTOK*NH*HD];
__device__ float g_x1 [(size_t)MTOK*HD];
__device__ float g_t1 [(size_t)MTOK*HD];
__device__ float g_hid[(size_t)MTOK*FF];

// ---------------- mma / ldmatrix helpers ----------------
__device__ __forceinline__ void mma16816(float* c, const unsigned* a, const unsigned* b)
{
    asm volatile(
        "mma.sync.aligned.m16n8k16.row.col.f32.bf16.bf16.f32 "
        "{%0,%1,%2,%3}, {%4,%5,%6,%7}, {%8,%9}, {%0,%1,%2,%3};\n"
        : "+f"(c[0]), "+f"(c[1]), "+f"(c[2]), "+f"(c[3])
        : "r"(a[0]), "r"(a[1]), "r"(a[2]), "r"(a[3]), "r"(b[0]), "r"(b[1]));
}

__device__ __forceinline__ void ldsm4(unsigned* d, unsigned addr)
{
    asm volatile("ldmatrix.sync.aligned.m8n8.x4.shared.b16 {%0,%1,%2,%3}, [%4];"
                 : "=r"(d[0]), "=r"(d[1]), "=r"(d[2]), "=r"(d[3]) : "r"(addr));
}

__device__ __forceinline__ void ldsm4t(unsigned* d, unsigned addr)
{
    asm volatile("ldmatrix.sync.aligned.m8n8.x4.trans.shared.b16 {%0,%1,%2,%3}, [%4];"
                 : "=r"(d[0]), "=r"(d[1]), "=r"(d[2]), "=r"(d[3]) : "r"(addr));
}

__device__ __forceinline__ unsigned ld32s(const __nv_bfloat16* p)
{
    return *reinterpret_cast<const unsigned*>(p);
}

// split (a,b) into packed bf16 hi and lo pairs
__device__ __forceinline__ void packsplit(float a, float b, unsigned& hi, unsigned& lo)
{
    __nv_bfloat16 ah = __float2bfloat16_rn(a);
    __nv_bfloat16 bh = __float2bfloat16_rn(b);
    __nv_bfloat162 h = __halves2bfloat162(ah, bh);
    __nv_bfloat162 l = __floats2bfloat162_rn(a - __bfloat162float(ah),
                                             b - __bfloat162float(bh));
    hi = *reinterpret_cast<unsigned*>(&h);
    lo = *reinterpret_cast<unsigned*>(&l);
}

// split a float4 into hi/lo bf16 pairs and store 8B each
__device__ __forceinline__ void split_store(__nv_bfloat16* hi_p, __nv_bfloat16* lo_p, float4 v)
{
    unsigned h01, l01, h23, l23;
    packsplit(v.x, v.y, h01, l01);
    packsplit(v.z, v.w, h23, l23);
    uint2 uh = make_uint2(h01, h23);
    uint2 ul = make_uint2(l01, l23);
    *reinterpret_cast<uint2*>(hi_p) = uh;
    *reinterpret_cast<uint2*>(lo_p) = ul;
}

// =================================================================
// bf16x3 split-precision tensor-core GEMM: C[M,N] = A[M,K]*B[N,K]^T
// Tiles: BM=128, BN=128, BK=32. 256 threads (8 warps of 64x32).
// SPLIT=1: write bf16 hi/lo outputs instead of fp32.
// =================================================================
#define ASTR 40
#define GEMM_SMEM (2*2*128*ASTR*2*2)   // 81920 B

template<int RELU, int SPLIT>
__device__ __forceinline__ void gemm_core(
    const float* __restrict__ A, const float* __restrict__ Bw,
    const float* __restrict__ bias, float* __restrict__ C,
    __nv_bfloat16* __restrict__ Chi, __nv_bfloat16* __restrict__ Clo,
    int N, int K, int m0, int n0)
{
    extern __shared__ __nv_bfloat16 sm_bf[];
    __nv_bfloat16* sA = sm_bf;
    __nv_bfloat16* sB = sm_bf + 2*2*128*ASTR;

    const int tid  = threadIdx.x;
    const int lane = tid & 31, warp = tid >> 5;
    const int wm = (warp >> 2) << 6;
    const int wn = (warp & 3)  << 5;
    const int g = lane >> 2, t = lane & 3;
    const int KT = K >> 5;

    float acc[4][4][4];
    #pragma unroll
    for (int i = 0; i < 4; i++)
        #pragma unroll
        for (int j = 0; j < 4; j++)
            #pragma unroll
            for (int q = 0; q < 4; q++) acc[i][j][q] = 0.f;

    float4 rA[4], rB[4];
    const float* Ag = A  + (size_t)m0 * K;
    const float* Bg = Bw + (size_t)n0 * K;

    #pragma unroll
    for (int i = 0; i < 4; i++) {
        int idx = i * 256 + tid;
        int r = idx >> 3, c = (idx & 7) << 2;
        rA[i] = *(const float4*)(Ag + (size_t)r * K + c);
        rB[i] = *(const float4*)(Bg + (size_t)r * K + c);
    }
    #pragma unroll
    for (int i = 0; i < 4; i++) {
        int idx = i * 256 + tid;
        int r = idx >> 3, c = (idx & 7) << 2;
        split_store(&sA[(0*128 + r)*ASTR + c], &sA[(1*128 + r)*ASTR + c], rA[i]);
        split_store(&sB[(0*128 + r)*ASTR + c], &sB[(1*128 + r)*ASTR + c], rB[i]);
    }
    __syncthreads();

    for (int kt = 0; kt < KT; kt++) {
        const int buf = kt & 1;
        if (kt + 1 < KT) {
            const int ko = (kt + 1) << 5;
            #pragma unroll
            for (int i = 0; i < 4; i++) {
                int idx = i * 256 + tid;
                int r = idx >> 3, c = (idx & 7) << 2;
                rA[i] = *(const float4*)(Ag + (size_t)r * K + ko + c);
                rB[i] = *(const float4*)(Bg + (size_t)r * K + ko + c);
            }
        }

        #pragma unroll
        for (int ks = 0; ks < 2; ks++) {
            const int kc = (ks << 4) + (t << 1);
            unsigned ah[4][4], al[4][4], bh[4][2], bl[4][2];
            #pragma unroll
            for (int mt = 0; mt < 4; mt++) {
                const int r = wm + (mt << 4) + g;
                const __nv_bfloat16* ph = &sA[((buf*2 + 0)*128 + r)*ASTR + kc];
                const __nv_bfloat16* pl = &sA[((buf*2 + 1)*128 + r)*ASTR + kc];
                ah[mt][0] = ld32s(ph);             ah[mt][1] = ld32s(ph + 8*ASTR);
                ah[mt][2] = ld32s(ph + 8);         ah[mt][3] = ld32s(ph + 8*ASTR + 8);
                al[mt][0] = ld32s(pl);             al[mt][1] = ld32s(pl + 8*ASTR);
                al[mt][2] = ld32s(pl + 8);         al[mt][3] = ld32s(pl + 8*ASTR + 8);
            }
            #pragma unroll
            for (int nt = 0; nt < 4; nt++) {
                const int r = wn + (nt << 3) + g;
                const __nv_bfloat16* ph = &sB[((buf*2 + 0)*128 + r)*ASTR + kc];
                const __nv_bfloat16* pl = &sB[((buf*2 + 1)*128 + r)*ASTR + kc];
                bh[nt][0] = ld32s(ph); bh[nt][1] = ld32s(ph + 8);
                bl[nt][0] = ld32s(pl); bl[nt][1] = ld32s(pl + 8);
            }
            #pragma unroll
            for (int mt = 0; mt < 4; mt++)
                #pragma unroll
                for (int nt = 0; nt < 4; nt++) {
                    mma16816(acc[mt][nt], ah[mt], bh[nt]);
                    mma16816(acc[mt][nt], ah[mt], bl[nt]);
                    mma16816(acc[mt][nt], al[mt], bh[nt]);
                }
        }

        if (kt + 1 < KT) {
            const int nb = buf ^ 1;
            #pragma unroll
            for (int i = 0; i < 4; i++) {
                int idx = i * 256 + tid;
                int r = idx >> 3, c = (idx & 7) << 2;
                split_store(&sA[((nb*2 + 0)*128 + r)*ASTR + c],
                            &sA[((nb*2 + 1)*128 + r)*ASTR + c], rA[i]);
                split_store(&sB[((nb*2 + 0)*128 + r)*ASTR + c],
                            &sB[((nb*2 + 1)*128 + r)*ASTR + c], rB[i]);
            }
        }
        __syncthreads();
    }

    #pragma unroll
    for (int mt = 0; mt < 4; mt++) {
        const int row = m0 + wm + (mt << 4) + g;
        #pragma unroll
        for (int nt = 0; nt < 4; nt++) {
            const int col = n0 + wn + (nt << 3) + (t << 1);
            float bx = 0.f, by = 0.f;
            if (bias) { bx = bias[col]; by = bias[col + 1]; }
            float v0 = acc[mt][nt][0] + bx, v1 = acc[mt][nt][1] + by;
            float v2 = acc[mt][nt][2] + bx, v3 = acc[mt][nt][3] + by;
            if (RELU) {
                v0 = fmaxf(v0, 0.f); v1 = fmaxf(v1, 0.f);
                v2 = fmaxf(v2, 0.f); v3 = fmaxf(v3, 0.f);
            }
            if (SPLIT) {
                unsigned h01, l01, h23, l23;
                packsplit(v0, v1, h01, l01);
                packsplit(v2, v3, h23, l23);
                *(unsigned*)(Chi + (size_t)row * N + col)       = h01;
                *(unsigned*)(Clo + (size_t)row * N + col)       = l01;
                *(unsigned*)(Chi + (size_t)(row + 8) * N + col) = h23;
                *(unsigned*)(Clo + (size_t)(row + 8) * N + col) = l23;
            } else {
                *(float2*)(C + (size_t)row * N + col)       = make_float2(v0, v1);
                *(float2*)(C + (size_t)(row + 8) * N + col) = make_float2(v2, v3);
            }
        }
    }
}

template<int RELU>
__global__ __launch_bounds__(256, 1) void gemm_mma_kernel(
    const float* __restrict__ A, const float* __restrict__ Bw,
    const float* __restrict__ bias, float* __restrict__ C, int N, int K)
{
    gemm_core<RELU, 0>(A, Bw, bias, C, nullptr, nullptr, N, K,
                       blockIdx.y << 7, blockIdx.x << 7);
}

// batched QKV with bf16 hi/lo split outputs
__global__ __launch_bounds__(256, 1) void gemm_qkv_kernel(
    const float* __restrict__ x,
    const float* __restrict__ wq, const float* __restrict__ wk, const float* __restrict__ wv,
    __nv_bfloat16* __restrict__ qh, __nv_bfloat16* __restrict__ ql,
    __nv_bfloat16* __restrict__ kh, __nv_bfloat16* __restrict__ kl,
    __nv_bfloat16* __restrict__ vh, __nv_bfloat16* __restrict__ vl)
{
    const int z = blockIdx.z;
    const int mat = z >> 2, h = z & 3;
    const float* Bw = (mat == 0 ? wq : mat == 1 ? wk : wv) + (size_t)h * HD * HD;
    __nv_bfloat16* Chi = (mat == 0 ? qh : mat == 1 ? kh : vh) + (size_t)h * MTOK * HD;
    __nv_bfloat16* Clo = (mat == 0 ? ql : mat == 1 ? kl : vl) + (size_t)h * MTOK * HD;
    gemm_core<0, 1>(x, Bw, nullptr, nullptr, Chi, Clo, HD, HD,
                    blockIdx.y << 7, blockIdx.x << 7);
}

// =================================================================
// flash attention on mma.sync (bf16 hi/lo), causal + padding mask
// CTA: 64 q-rows, 4 warps x 16 rows; 64-key tiles; HD=256.
// =================================================================
#define QS 264
#define FLASH_SMEM (6*64*QS*2)   // 202752 B
#define L2E 1.4426950408889634f

__global__ __launch_bounds__(128, 1) void flash_mma_kernel(
    const __nv_bfloat16* __restrict__ qh, const __nv_bfloat16* __restrict__ ql,
    const __nv_bfloat16* __restrict__ kh, const __nv_bfloat16* __restrict__ kl,
    const __nv_bfloat16* __restrict__ vh, const __nv_bfloat16* __restrict__ vl,
    const int* __restrict__ amask, float* __restrict__ outc)
{
    extern __shared__ __nv_bfloat16 sm[];
    __nv_bfloat16* sQh = sm;
    __nv_bfloat16* sQl = sQh + 64*QS;
    __nv_bfloat16* sKh = sQl + 64*QS;
    __nv_bfloat16* sKl = sKh + 64*QS;
    __nv_bfloat16* sVh = sKl + 64*QS;
    __nv_bfloat16* sVl = sVh + 64*QS;
    __shared__ int sMq[64];
    __shared__ int sMk[64];

    const int tid  = threadIdx.x;
    const int lane = tid & 31, w = tid >> 5;
    const int g = lane >> 2, t = lane & 3;
    const int bh = blockIdx.y;
    const int b = bh >> 2, h = bh & 3;
    const int qidx = (int)gridDim.x - 1 - (int)blockIdx.x;   // heavy CTAs first
    const int m0 = qidx << 6;
    const size_t base = ((size_t)h * MTOK + (size_t)b * SEQ) * HD;

    const unsigned bQh = (unsigned)__cvta_generic_to_shared(sQh);
    const unsigned bQl = (unsigned)__cvta_generic_to_shared(sQl);
    const unsigned bKh = (unsigned)__cvta_generic_to_shared(sKh);
    const unsigned bKl = (unsigned)__cvta_generic_to_shared(sKl);
    const unsigned bVh = (unsigned)__cvta_generic_to_shared(sVh);
    const unsigned bVl = (unsigned)__cvta_generic_to_shared(sVl);

    // per-lane ldmatrix byte offsets
    const unsigned offA = (((w << 4) + (lane & 15)) * QS + ((lane >> 4) << 3)) * 2;
    const unsigned offB = ((((lane & 7) | ((lane >> 1) & 8)) * QS) + (lane & 8)) * 2;
    const unsigned offV = (((lane & 15) * QS) + ((lane >> 4) << 3)) * 2;

    // load Q tile (both splits) + query mask
    {
        const __nv_bfloat16* Qh = qh + base + (size_t)m0 * HD;
        const __nv_bfloat16* Ql = ql + base + (size_t)m0 * HD;
        for (int i = tid; i < 2048; i += 128) {
            int r = i >> 5, c = (i & 31) << 3;
            *(uint4*)&sQh[r*QS + c] = *(const uint4*)(Qh + (size_t)r*HD + c);
            *(uint4*)&sQl[r*QS + c] = *(const uint4*)(Ql + (size_t)r*HD + c);
        }
        if (tid < 64) sMq[tid] = amask[b * SEQ + m0 + tid];
    }

    float accO[32][4];
    #pragma unroll
    for (int i = 0; i < 32; i++)
        #pragma unroll
        for (int j = 0; j < 4; j++) accO[i][j] = 0.f;
    float m_run0 = -1e30f, m_run1 = -1e30f, l_run0 = 0.f, l_run1 = 0.f;

    const int gi0 = m0 + (w << 4) + g;
    const int gi1 = gi0 + 8;

    const int ntiles = qidx + 1;
    for (int kt = 0; kt < ntiles; kt++) {
        const int j0 = kt << 6;
        __syncthreads();
        {
            const __nv_bfloat16* Kh = kh + base + (size_t)j0 * HD;
            const __nv_bfloat16* Kl = kl + base + (size_t)j0 * HD;
            const __nv_bfloat16* Vh = vh + base + (size_t)j0 * HD;
            const __nv_bfloat16* Vl = vl + base + (size_t)j0 * HD;
            for (int i = tid; i < 2048; i += 128) {
                int r = i >> 5, c = (i & 31) << 3;
                *(uint4*)&sKh[r*QS + c] = *(const uint4*)(Kh + (size_t)r*HD + c);
                *(uint4*)&sKl[r*QS + c] = *(const uint4*)(Kl + (size_t)r*HD + c);
                *(uint4*)&sVh[r*QS + c] = *(const uint4*)(Vh + (size_t)r*HD + c);
                *(uint4*)&sVl[r*QS + c] = *(const uint4*)(Vl + (size_t)r*HD + c);
            }
            if (tid < 64) sMk[tid] = amask[b * SEQ + j0 + tid];
        }
        __syncthreads();

        // ---- scores: sc[nt][4] over 8 n-tiles (64 keys) ----
        float sc[8][4];
        #pragma unroll
        for (int i = 0; i < 8; i++)
            #pragma unroll
            for (int j = 0; j < 4; j++) sc[i][j] = 0.f;

        #pragma unroll 4
        for (int ks = 0; ks < 16; ks++) {
            unsigned aqh[4], aql[4];
            ldsm4(aqh, bQh + offA + ks*32);
            ldsm4(aql, bQl + offA + ks*32);
            #pragma unroll
            for (int p = 0; p < 4; p++) {
                unsigned kbh[4], kbl[4];
                ldsm4(kbh, bKh + offB + p*(16*QS*2) + ks*32);
                ldsm4(kbl, bKl + offB + p*(16*QS*2) + ks*32);
                mma16816(sc[2*p],   aqh, kbh);
                mma16816(sc[2*p],   aqh, kbl);
                mma16816(sc[2*p],   aql, kbh);
                mma16816(sc[2*p+1], aqh, kbh+2);
                mma16816(sc[2*p+1], aqh, kbl+2);
                mma16816(sc[2*p+1], aql, kbh+2);
            }
        }

        // ---- mask + online softmax on fragments ----
        const int qm0 = sMq[(w << 4) + g];
        const int qm1 = sMq[(w << 4) + g + 8];
        float mx0 = -1e30f, mx1 = -1e30f;
        #pragma unroll
        for (int nt = 0; nt < 8; nt++) {
            const int jb = (nt << 3) + (t << 1);
            const int k0 = sMk[jb], k1 = sMk[jb + 1];
            const int gj0 = j0 + jb, gj1 = gj0 + 1;
            sc[nt][0] = (qm0 && k0 && gj0 <= gi0) ? sc[nt][0] * 0.0625f : -1e30f;
            sc[nt][1] = (qm0 && k1 && gj1 <= gi0) ? sc[nt][1] * 0.0625f : -1e30f;
            sc[nt][2] = (qm1 && k0 && gj0 <= gi1) ? sc[nt][2] * 0.0625f : -1e30f;
            sc[nt][3] = (qm1 && k1 && gj1 <= gi1) ? sc[nt][3] * 0.0625f : -1e30f;
            mx0 = fmaxf(mx0, fmaxf(sc[nt][0], sc[nt][1]));
            mx1 = fmaxf(mx1, fmaxf(sc[nt][2], sc[nt][3]));
        }
        mx0 = fmaxf(mx0, __shfl_xor_sync(0xffffffffu, mx0, 1, 4));
        mx0 = fmaxf(mx0, __shfl_xor_sync(0xffffffffu, mx0, 2, 4));
        mx1 = fmaxf(mx1, __shfl_xor_sync(0xffffffffu, mx1, 1, 4));
        mx1 = fmaxf(mx1, __shfl_xor_sync(0xffffffffu, mx1, 2, 4));

        const float mn0 = fmaxf(m_run0, mx0);
        const float mn1 = fmaxf(m_run1, mx1);
        const float al0 = exp2f((m_run0 - mn0) * L2E);
        const float al1 = exp2f((m_run1 - mn1) * L2E);
        m_run0 = mn0; m_run1 = mn1;

        float ps0 = 0.f, ps1 = 0.f;
        #pragma unroll
        for (int nt = 0; nt < 8; nt++) {
            float p0 = exp2f((sc[nt][0] - mn0) * L2E);
            float p1 = exp2f((sc[nt][1] - mn0) * L2E);
            float p2 = exp2f((sc[nt][2] - mn1) * L2E);
            float p3 = exp2f((sc[nt][3] - mn1) * L2E);
            sc[nt][0] = p0; sc[nt][1] = p1; sc[nt][2] = p2; sc[nt][3] = p3;
            ps0 += p0 + p1; ps1 += p2 + p3;
        }
        ps0 += __shfl_xor_sync(0xffffffffu, ps0, 1, 4);
        ps0 += __shfl_xor_sync(0xffffffffu, ps0, 2, 4);
        ps1 += __shfl_xor_sync(0xffffffffu, ps1, 1, 4);
        ps1 += __shfl_xor_sync(0xffffffffu, ps1, 2, 4);
        l_run0 = l_run0 * al0 + ps0;
        l_run1 = l_run1 * al1 + ps1;

        #pragma unroll
        for (int i = 0; i < 32; i++) {
            accO[i][0] *= al0; accO[i][1] *= al0;
            accO[i][2] *= al1; accO[i][3] *= al1;
        }

        // ---- O += P * V ----
        #pragma unroll
        for (int ks = 0; ks < 4; ks++) {
            unsigned aPh[4], aPl[4];
            packsplit(sc[2*ks][0],   sc[2*ks][1],   aPh[0], aPl[0]);
            packsplit(sc[2*ks][2],   sc[2*ks][3],   aPh[1], aPl[1]);
            packsplit(sc[2*ks+1][0], sc[2*ks+1][1], aPh[2], aPl[2]);
            packsplit(sc[2*ks+1][2], sc[2*ks+1][3], aPh[3], aPl[3]);
            #pragma unroll
            for (int nv = 0; nv < 16; nv++) {
                unsigned vbh[4], vbl[4];
                ldsm4t(vbh, bVh + offV + ks*(16*QS*2) + nv*32);
                ldsm4t(vbl, bVl + offV + ks*(16*QS*2) + nv*32);
                mma16816(accO[2*nv],   aPh, vbh);
                mma16816(accO[2*nv],   aPh, vbl);
                mma16816(accO[2*nv],   aPl, vbh);
                mma16816(accO[2*nv+1], aPh, vbh+2);
                mma16816(accO[2*nv+1], aPh, vbl+2);
                mma16816(accO[2*nv+1], aPl, vbh+2);
            }
        }
    }

    // ---- epilogue ----
    const int qm0 = sMq[(w << 4) + g];
    const int qm1 = sMq[(w << 4) + g + 8];
    const float inv0 = (qm0 && l_run0 > 0.f) ? (1.f / l_run0) : 0.f;
    const float inv1 = (qm1 && l_run1 > 0.f) ? (1.f / l_run1) : 0.f;
    float* o0 = outc + (size_t)(b * SEQ + gi0) * (NH * HD) + h * HD;
    float* o1 = outc + (size_t)(b * SEQ + gi1) * (NH * HD) + h * HD;
    #pragma unroll
    for (int nt = 0; nt < 32; nt++) {
        const int col = (nt << 3) + (t << 1);
        *(float2*)(o0 + col) = make_float2(accO[nt][0] * inv0, accO[nt][1] * inv0);
        *(float2*)(o1 + col) = make_float2(accO[nt][2] * inv1, accO[nt][3] * inv1);
    }
}

// ---------------- fused residual-add + LayerNorm ----------------
__global__ __launch_bounds__(256) void add_ln_kernel(
    const float* __restrict__ a, const float* __restrict__ b2,
    const float* __restrict__ g, const float* __restrict__ be,
    float* __restrict__ out)
{
    __shared__ float red[16];
    const int row = blockIdx.x, t = threadIdx.x;
    const size_t off = (size_t)row * HD + t;
    const float v = a[off] + b2[off];
    float sv = v, sq = v * v;
    #pragma unroll
    for (int o = 16; o; o >>= 1) {
        sv += __shfl_xor_sync(0xffffffffu, sv, o);
        sq += __shfl_xor_sync(0xffffffffu, sq, o);
    }
    if ((t & 31) == 0) { red[t >> 5] = sv; red[8 + (t >> 5)] = sq; }
    __syncthreads();
    if (t == 0) {
        float s1 = 0.f, s2 = 0.f;
        #pragma unroll
        for (int i = 0; i < 8; i++) { s1 += red[i]; s2 += red[8 + i]; }
        red[0] = s1; red[8] = s2;
    }
    __syncthreads();
    const float mu  = red[0] * (1.f / 256.f);
    const float var = red[8] * (1.f / 256.f) - mu * mu;
    out[off] = (v - mu) * rsqrtf(var + 1e-5f) * g[t] + be[t];
}

// ---------------- launch ----------------
extern "C" void kernel_launch(void* const* d_in, const int* in_sizes, int n_in,
                              void* d_out, int out_size)
{
    const float* x    = (const float*)d_in[0];
    const int*   am   = (const int*  )d_in[1];
    const float* wq   = (const float*)d_in[2];
    const float* wk   = (const float*)d_in[3];
    const float* wv   = (const float*)d_in[4];
    const float* wo_w = (const float*)d_in[5];
    const float* wo_b = (const float*)d_in[6];
    const float* ln1g = (const float*)d_in[7];
    const float* ln1b = (const float*)d_in[8];
    const float* f1w  = (const float*)d_in[9];
    const float* f1b  = (const float*)d_in[10];
    const float* f2w  = (const float*)d_in[11];
    const float* f2b  = (const float*)d_in[12];
    const float* ln2g = (const float*)d_in[13];
    const float* ln2b = (const float*)d_in[14];
    float* out = (float*)d_out;
    (void)in_sizes; (void)n_in; (void)out_size;

    __nv_bfloat16 *pqh, *pql, *pkh, *pkl, *pvh, *pvl;
    float *patt, *px1, *pt1, *phid;
    cudaGetSymbolAddress((void**)&pqh, g_qh);
    cudaGetSymbolAddress((void**)&pql, g_ql);
    cudaGetSymbolAddress((void**)&pkh, g_kh);
    cudaGetSymbolAddress((void**)&pkl, g_kl);
    cudaGetSymbolAddress((void**)&pvh, g_vh);
    cudaGetSymbolAddress((void**)&pvl, g_vl);
    cudaGetSymbolAddress((void**)&patt, g_att);
    cudaGetSymbolAddress((void**)&px1,  g_x1);
    cudaGetSymbolAddress((void**)&pt1,  g_t1);
    cudaGetSymbolAddress((void**)&phid, g_hid);

    cudaFuncSetAttribute(gemm_qkv_kernel,    cudaFuncAttributeMaxDynamicSharedMemorySize, GEMM_SMEM);
    cudaFuncSetAttribute(gemm_mma_kernel<0>, cudaFuncAttributeMaxDynamicSharedMemorySize, GEMM_SMEM);
    cudaFuncSetAttribute(gemm_mma_kernel<1>, cudaFuncAttributeMaxDynamicSharedMemorySize, GEMM_SMEM);
    cudaFuncSetAttribute(flash_mma_kernel,   cudaFuncAttributeMaxDynamicSharedMemorySize, FLASH_SMEM);

    const dim3 blk(256);

    // ---- QKV projections (bf16 hi/lo outputs) ----
    gemm_qkv_kernel<<<dim3(HD/128, MTOK/128, 12), blk, GEMM_SMEM>>>(
        x, wq, wk, wv, pqh, pql, pkh, pkl, pvh, pvl);

    // ---- causal flash attention on tensor cores ----
    flash_mma_kernel<<<dim3(SEQ/64, BATCH*NH), dim3(128), FLASH_SMEM>>>(
        pqh, pql, pkh, pkl, pvh, pvl, am, patt);

    // ---- output projection + residual/LN1 ----
    gemm_mma_kernel<0><<<dim3(HD/128, MTOK/128), blk, GEMM_SMEM>>>(patt, wo_w, wo_b, pt1, HD, NH*HD);
    add_ln_kernel<<<MTOK, blk>>>(x, pt1, ln1g, ln1b, px1);

    // ---- FFN + residual/LN2 ----
    gemm_mma_kernel<1><<<dim3(FF/128, MTOK/128), blk, GEMM_SMEM>>>(px1, f1w, f1b, phid, FF, HD);
    gemm_mma_kernel<0><<<dim3(HD/128, MTOK/128), blk, GEMM_SMEM>>>(phid, f2w, f2b, pt1, HD, FF);
    add_ln_kernel<<<MTOK, blk>>>(px1, pt1, ln2g, ln2b, out);
}